// round 7
// baseline (speedup 1.0000x reference)
#include <cuda_runtime.h>
#include <cstdint>

#define MAX_N 100000
#define IN_DIM 192
#define NEG_SLOPE 0.2f
#define EDGE_ILP 4

// Scratch (allocation-free rule: __device__ globals).
// g_rec[n]  = {xproj0, xproj1, a_src, a_dst}
// g_adst[n] = a_dst packed (8 nodes/sector -> better L1 behavior on gathers)
// g_acc[n]  = {sum e*xp0, sum e*xp1, sum e, pad}
__device__ float4 g_rec[MAX_N];
__device__ float  g_adst[MAX_N];
__device__ float4 g_acc[MAX_N];
__device__ int    g_is64;   // 1 if edge_index is int64, 0 if int32

// ---------------------------------------------------------------------------
// Kernel 1: projection + logits + self-loop init; half-warp per node.
// Lanes 0-15 -> node 2w, lanes 16-31 -> node 2w+1. 3x LDG.128 per lane
// (coalesced 512B/warp/instr), 24 FFMA, 4-step width-16 shuffle reduce,
// two store lanes per warp. Block 0 warp 0 also runs the int64 detector.
// ---------------------------------------------------------------------------
__global__ __launch_bounds__(256)
void gat_project_kernel(const float* __restrict__ x,
                        const float* __restrict__ W,        // [IN_DIM,2]
                        const float* __restrict__ att_src,  // [2]
                        const float* __restrict__ att_dst,  // [2]
                        const int* __restrict__ eidx_w,     // edge_index as words
                        int det_nwords,                     // 0 => force is64=1
                        int N)
{
    if (blockIdx.x == 0 && threadIdx.x < 32) {
        int notz = 0;
        if (det_nwords > 0) {
            for (int i = threadIdx.x; i < 2048; i += 32) {
                int p = 2 * i + 1;
                if (p < det_nwords && eidx_w[p] != 0) notz = 1;
            }
        }
        notz = __any_sync(0xffffffffu, notz);
        if (threadIdx.x == 0) g_is64 = (det_nwords > 0) ? (notz ? 0 : 1) : 1;
    }

    int lane  = threadIdx.x & 31;
    int hl    = lane & 15;                // lane within half-warp
    int half  = lane >> 4;                // which node of the pair
    int warp  = (blockIdx.x * blockDim.x + threadIdx.x) >> 5;
    int nwarp = (gridDim.x * blockDim.x) >> 5;

    // W float4 q covers rows 2q,2q+1 -> {W[2q][0],W[2q][1],W[2q+1][0],W[2q+1][1]}
    // lane needs element blocks 4hl.., 4hl+64.., 4hl+128.. -> 6 W float4s
    const float4* W4 = (const float4*)W;
    float4 wA = __ldg(W4 + 2 * hl);
    float4 wB = __ldg(W4 + 2 * hl + 1);
    float4 wC = __ldg(W4 + 2 * hl + 32);
    float4 wD = __ldg(W4 + 2 * hl + 33);
    float4 wE = __ldg(W4 + 2 * hl + 64);
    float4 wF = __ldg(W4 + 2 * hl + 65);
    float as0 = __ldg(att_src + 0), as1 = __ldg(att_src + 1);
    float ad0 = __ldg(att_dst + 0), ad1 = __ldg(att_dst + 1);

    for (int n0 = 2 * warp; n0 < N; n0 += 2 * nwarp) {
        int n = n0 + half;                       // this half-warp's node
        int nc = (n < N) ? n : (N - 1);          // clamp for safe load
        const float4* xr = (const float4*)(x + (size_t)nc * IN_DIM);
        float4 v0 = __ldg(xr + hl);
        float4 v1 = __ldg(xr + hl + 16);
        float4 v2 = __ldg(xr + hl + 32);

        float p0 = v0.x * wA.x + v0.y * wA.z + v0.z * wB.x + v0.w * wB.z
                 + v1.x * wC.x + v1.y * wC.z + v1.z * wD.x + v1.w * wD.z
                 + v2.x * wE.x + v2.y * wE.z + v2.z * wF.x + v2.w * wF.z;
        float p1 = v0.x * wA.y + v0.y * wA.w + v0.z * wB.y + v0.w * wB.w
                 + v1.x * wC.y + v1.y * wC.w + v1.z * wD.y + v1.w * wD.w
                 + v2.x * wE.y + v2.y * wE.w + v2.z * wF.y + v2.w * wF.w;

#pragma unroll
        for (int off = 8; off > 0; off >>= 1) {   // width-16 reduce
            p0 += __shfl_xor_sync(0xffffffffu, p0, off);
            p1 += __shfl_xor_sync(0xffffffffu, p1, off);
        }

        if (hl == 0 && n < N) {
            float a_s = p0 * as0 + p1 * as1;
            float a_d = p0 * ad0 + p1 * ad1;
            g_rec[n]  = make_float4(p0, p1, a_s, a_d);
            g_adst[n] = a_d;
            float alpha = a_s + a_d;              // self-loop edge
            alpha = (alpha >= 0.f) ? alpha : NEG_SLOPE * alpha;
            float ev = __expf(alpha);
            g_acc[n] = make_float4(ev * p0, ev * p1, ev, 0.f);
        }
    }
}

// ---------------------------------------------------------------------------
// Kernel 2: single fused pass over edges, ILP=4, full grid. L1tex-wavefront
// bound at ~3.25 wf/edge. Non-tail blocks skip the e<E predicates.
//   alpha = leakyrelu(a_src[s] + a_dst[d]); e = exp(alpha)
//   acc[d] += {e*xp0[s], e*xp1[s], e, 0}  via one red.global.add.v4.f32
// (softmax max-subtraction elided: scale-invariant; fp32-safe here)
// ---------------------------------------------------------------------------
__global__ __launch_bounds__(256)
void gat_edge_kernel(const void* __restrict__ edge_index, int E, int N)
{
    int base = blockIdx.x * (256 * EDGE_ILP) + threadIdx.x;
    int is64 = g_is64;
    bool full = (blockIdx.x + 1) * (256 * EDGE_ILP) <= E;

    int s[EDGE_ILP], d[EDGE_ILP];
    if (full) {
#pragma unroll
        for (int i = 0; i < EDGE_ILP; i++) {
            int e = base + i * 256;
            if (is64) {
                const long long* ei = (const long long*)edge_index;
                s[i] = (int)__ldg(ei + e);
                d[i] = (int)__ldg(ei + E + e);
            } else {
                const int* ei = (const int*)edge_index;
                s[i] = __ldg(ei + e);
                d[i] = __ldg(ei + E + e);
            }
        }
    } else {
#pragma unroll
        for (int i = 0; i < EDGE_ILP; i++) {
            int e = base + i * 256;
            s[i] = -1; d[i] = -1;
            if (e < E) {
                if (is64) {
                    const long long* ei = (const long long*)edge_index;
                    s[i] = (int)__ldg(ei + e);
                    d[i] = (int)__ldg(ei + E + e);
                } else {
                    const int* ei = (const int*)edge_index;
                    s[i] = __ldg(ei + e);
                    d[i] = __ldg(ei + E + e);
                }
            }
        }
    }

    float4 rs[EDGE_ILP];
    float  ad[EDGE_ILP];
#pragma unroll
    for (int i = 0; i < EDGE_ILP; i++) {
        if ((unsigned)s[i] < (unsigned)N && (unsigned)d[i] < (unsigned)N) {
            rs[i] = __ldg(&g_rec[s[i]]);        // 16B gather
            ad[i] = __ldg(&g_adst[d[i]]);       // 4B gather, dense array
        }
    }

#pragma unroll
    for (int i = 0; i < EDGE_ILP; i++) {
        if ((unsigned)s[i] < (unsigned)N && (unsigned)d[i] < (unsigned)N) {
            float alpha = rs[i].z + ad[i];
            alpha = (alpha >= 0.f) ? alpha : NEG_SLOPE * alpha;
            float ev = __expf(alpha);
            float v0 = ev * rs[i].x;
            float v1 = ev * rs[i].y;
            asm volatile("red.global.add.v4.f32 [%0], {%1, %2, %3, %4};"
                         :: "l"(&g_acc[d[i]]), "f"(v0), "f"(v1), "f"(ev), "f"(0.f)
                         : "memory");
        }
    }
}

// ---------------------------------------------------------------------------
// Kernel 3: normalize + bias -> out[N,2].
// ---------------------------------------------------------------------------
__global__ __launch_bounds__(128)
void gat_final_kernel(float* __restrict__ out,
                      const float* __restrict__ bias,
                      int N)
{
    int n = blockIdx.x * blockDim.x + threadIdx.x;
    if (n >= N) return;
    float4 a = g_acc[n];
    float inv = 1.0f / (a.z + 1e-16f);
    float b0 = __ldg(bias + 0), b1 = __ldg(bias + 1);
    ((float2*)out)[n] = make_float2(a.x * inv + b0, a.y * inv + b1);
}

// ---------------------------------------------------------------------------
// Input identification by element count (robust to metadata ordering):
//   x = largest; edge_index = 2nd; edge_attr = 3rd (gives E); W = 384;
//   att_src, att_dst, bias = the three size-2 tensors in appearance order.
// ---------------------------------------------------------------------------
extern "C" void kernel_launch(void* const* d_in, const int* in_sizes, int n_in,
                              void* d_out, int out_size)
{
    int i_x = -1, i_eidx = -1, i_attr = -1, i_W = -1;
    int small[3] = {-1, -1, -1};
    int nsmall = 0;
    {
        long long best = -1;
        for (int i = 0; i < n_in; i++)
            if (in_sizes[i] > best) { best = in_sizes[i]; i_x = i; }
        best = -1;
        for (int i = 0; i < n_in; i++)
            if (i != i_x && in_sizes[i] > best) { best = in_sizes[i]; i_eidx = i; }
        best = -1;
        for (int i = 0; i < n_in; i++)
            if (i != i_x && i != i_eidx && in_sizes[i] > best) { best = in_sizes[i]; i_attr = i; }
    }
    for (int i = 0; i < n_in; i++) {
        if (i == i_x || i == i_eidx || i == i_attr) continue;
        if (in_sizes[i] > 16) { i_W = i; }
        else if (nsmall < 3) { small[nsmall++] = i; }
    }

    const float* x       = (const float*)d_in[i_x];
    const void*  eidx    = d_in[i_eidx];
    const float* W       = (const float*)d_in[i_W];
    const float* att_src = (const float*)d_in[small[0]];
    const float* att_dst = (const float*)d_in[small[1]];
    const float* bias    = (const float*)d_in[small[2]];
    float* out           = (float*)d_out;

    int N = in_sizes[i_x] / IN_DIM;
    int E = in_sizes[i_attr];               // edge_attr is [E,1]
    int eidx_elems = in_sizes[i_eidx];

    // dtype: ratio 4 => int64 reported as word count (det_nwords=0 => force 64).
    // ratio 2 => ambiguous; K1 block 0 samples odd words on device.
    int det_nwords = (eidx_elems == 4 * E) ? 0 : (2 * E);

    // K1: persistent, half-warp per node (2 nodes / warp / iter)
    gat_project_kernel<<<1184, 256>>>(x, W, att_src, att_dst,
                                      (const int*)eidx, det_nwords, N);

    // K2: ILP=4 edges per thread, full grid (max occupancy)
    int blocks2 = (E + 256 * EDGE_ILP - 1) / (256 * EDGE_ILP);
    gat_edge_kernel<<<blocks2, 256>>>(eidx, E, N);

    // K3: normalize + bias
    gat_final_kernel<<<(N + 127) / 128, 128>>>(out, bias, N);
}

// round 8
// speedup vs baseline: 1.0102x; 1.0102x over previous
#include <cuda_runtime.h>
#include <cstdint>

#define MAX_N 100000
#define IN_DIM 192
#define NEG_SLOPE 0.2f
#define EDGE_ILP 4
#define CHUNK 32
#define NCHUNK 6              // 192 / 32

// Scratch (allocation-free rule: __device__ globals).
// g_rec[n]  = {xproj0, xproj1, a_src, a_dst}
// g_adst[n] = a_dst packed (dense -> better L1 behavior on gathers)
// g_acc[n]  = {sum e*xp0, sum e*xp1, sum e, pad}
__device__ float4 g_rec[MAX_N];
__device__ float  g_adst[MAX_N];
__device__ float4 g_acc[MAX_N];
__device__ int    g_is64;     // 1 if edge_index is int64, 0 if int32

__constant__ float cW[2 * IN_DIM];   // W row-major [192][2]

// ---------------------------------------------------------------------------
// Kernel 1: projection + logits + self-loop init. Thread-per-node via
// smem-transposed tiles: no shuffles, no cross-thread chains.
//   per chunk: coalesced 8x LDG.128/thread -> transposed STS (stride 257,
//   conflict-free) -> 32x LDS + FFMA with W from __constant__.
// Block 0 warp 0 additionally runs the int64/int32 detector.
// ---------------------------------------------------------------------------
__global__ __launch_bounds__(256)
void gat_project_kernel(const float* __restrict__ x,
                        const float* __restrict__ att_src,  // [2]
                        const float* __restrict__ att_dst,  // [2]
                        const int* __restrict__ eidx_w,     // edge_index words
                        int det_nwords,                     // 0 => force is64=1
                        int N)
{
    __shared__ float xs[CHUNK * 257];   // [k][row], row-stride 257

    if (blockIdx.x == 0 && threadIdx.x < 32) {
        int notz = 0;
        if (det_nwords > 0) {
            for (int i = threadIdx.x; i < 2048; i += 32) {
                int p = 2 * i + 1;                 // odd 32-bit words
                if (p < det_nwords && eidx_w[p] != 0) notz = 1;
            }
        }
        notz = __any_sync(0xffffffffu, notz);
        if (threadIdx.x == 0) g_is64 = (det_nwords > 0) ? (notz ? 0 : 1) : 1;
    }

    const int t = threadIdx.x;
    const int node0 = blockIdx.x * 256;

    float p0 = 0.f, p1 = 0.f;

#pragma unroll
    for (int c = 0; c < NCHUNK; c++) {
        if (c) __syncthreads();                    // protect smem reuse

        // ---- staged coalesced load: rows (t+256j)>>3, float4 (t+256j)&7 ----
        float4 stage[8];
#pragma unroll
        for (int j = 0; j < 8; j++) {
            int idx = t + 256 * j;
            int row = idx >> 3;
            int f4  = idx & 7;
            int gn  = node0 + row;
            if (gn >= N) gn = N - 1;               // clamped (safe) load
            stage[j] = __ldg((const float4*)(x + (size_t)gn * IN_DIM + c * CHUNK) + f4);
        }
#pragma unroll
        for (int j = 0; j < 8; j++) {
            int idx = t + 256 * j;
            int row = idx >> 3;
            int kb  = (idx & 7) * 4;               // base k of this float4
            xs[(kb + 0) * 257 + row] = stage[j].x;
            xs[(kb + 1) * 257 + row] = stage[j].y;
            xs[(kb + 2) * 257 + row] = stage[j].z;
            xs[(kb + 3) * 257 + row] = stage[j].w;
        }
        __syncthreads();

        // ---- compute: thread t = node node0+t; W from constant bank ----
#pragma unroll
        for (int k = 0; k < CHUNK; k++) {
            float xv = xs[k * 257 + t];
            p0 = fmaf(xv, cW[(c * CHUNK + k) * 2 + 0], p0);
            p1 = fmaf(xv, cW[(c * CHUNK + k) * 2 + 1], p1);
        }
    }

    int n = node0 + t;
    if (n < N) {
        float as0 = __ldg(att_src + 0), as1 = __ldg(att_src + 1);
        float ad0 = __ldg(att_dst + 0), ad1 = __ldg(att_dst + 1);
        float a_s = p0 * as0 + p1 * as1;
        float a_d = p0 * ad0 + p1 * ad1;
        g_rec[n]  = make_float4(p0, p1, a_s, a_d);
        g_adst[n] = a_d;
        float alpha = a_s + a_d;                   // self-loop edge
        alpha = (alpha >= 0.f) ? alpha : NEG_SLOPE * alpha;
        float ev = __expf(alpha);
        g_acc[n] = make_float4(ev * p0, ev * p1, ev, 0.f);
    }
}

// ---------------------------------------------------------------------------
// Kernel 2 (unchanged from R6): single fused pass over edges, ILP=4.
//   alpha = leakyrelu(a_src[s] + a_dst[d]); e = exp(alpha)
//   acc[d] += {e*xp0[s], e*xp1[s], e, 0}  via one red.global.add.v4.f32
// (softmax max-subtraction elided: scale-invariant; fp32-safe here)
// ---------------------------------------------------------------------------
__global__ __launch_bounds__(256)
void gat_edge_kernel(const void* __restrict__ edge_index, int E, int N)
{
    int base = blockIdx.x * (256 * EDGE_ILP) + threadIdx.x;
    int is64 = g_is64;
    bool full = (blockIdx.x + 1) * (256 * EDGE_ILP) <= E;

    int s[EDGE_ILP], d[EDGE_ILP];
    if (full) {
#pragma unroll
        for (int i = 0; i < EDGE_ILP; i++) {
            int e = base + i * 256;
            if (is64) {
                const long long* ei = (const long long*)edge_index;
                s[i] = (int)__ldg(ei + e);
                d[i] = (int)__ldg(ei + E + e);
            } else {
                const int* ei = (const int*)edge_index;
                s[i] = __ldg(ei + e);
                d[i] = __ldg(ei + E + e);
            }
        }
    } else {
#pragma unroll
        for (int i = 0; i < EDGE_ILP; i++) {
            int e = base + i * 256;
            s[i] = -1; d[i] = -1;
            if (e < E) {
                if (is64) {
                    const long long* ei = (const long long*)edge_index;
                    s[i] = (int)__ldg(ei + e);
                    d[i] = (int)__ldg(ei + E + e);
                } else {
                    const int* ei = (const int*)edge_index;
                    s[i] = __ldg(ei + e);
                    d[i] = __ldg(ei + E + e);
                }
            }
        }
    }

    float4 rs[EDGE_ILP];
    float  ad[EDGE_ILP];
#pragma unroll
    for (int i = 0; i < EDGE_ILP; i++) {
        if ((unsigned)s[i] < (unsigned)N && (unsigned)d[i] < (unsigned)N) {
            rs[i] = __ldg(&g_rec[s[i]]);        // 16B gather
            ad[i] = __ldg(&g_adst[d[i]]);       // 4B gather, dense array
        }
    }

#pragma unroll
    for (int i = 0; i < EDGE_ILP; i++) {
        if ((unsigned)s[i] < (unsigned)N && (unsigned)d[i] < (unsigned)N) {
            float alpha = rs[i].z + ad[i];
            alpha = (alpha >= 0.f) ? alpha : NEG_SLOPE * alpha;
            float ev = __expf(alpha);
            float v0 = ev * rs[i].x;
            float v1 = ev * rs[i].y;
            asm volatile("red.global.add.v4.f32 [%0], {%1, %2, %3, %4};"
                         :: "l"(&g_acc[d[i]]), "f"(v0), "f"(v1), "f"(ev), "f"(0.f)
                         : "memory");
        }
    }
}

// ---------------------------------------------------------------------------
// Kernel 3: normalize + bias. 2 nodes/thread, packed float4 store.
// ---------------------------------------------------------------------------
__global__ __launch_bounds__(256)
void gat_final_kernel(float* __restrict__ out,
                      const float* __restrict__ bias,
                      int N)
{
    int i = blockIdx.x * blockDim.x + threadIdx.x;   // pair index
    int n0 = 2 * i;
    if (n0 >= N) return;
    float b0 = __ldg(bias + 0), b1 = __ldg(bias + 1);

    float4 a0 = g_acc[n0];
    float inv0 = 1.0f / (a0.z + 1e-16f);
    if (n0 + 1 < N) {
        float4 a1 = g_acc[n0 + 1];
        float inv1 = 1.0f / (a1.z + 1e-16f);
        float4 o = make_float4(a0.x * inv0 + b0, a0.y * inv0 + b1,
                               a1.x * inv1 + b0, a1.y * inv1 + b1);
        ((float4*)out)[i] = o;
    } else {
        ((float2*)out)[n0] = make_float2(a0.x * inv0 + b0, a0.y * inv0 + b1);
    }
}

// ---------------------------------------------------------------------------
// Input identification by element count (robust to metadata ordering):
//   x = largest; edge_index = 2nd; edge_attr = 3rd (gives E); W = 384;
//   att_src, att_dst, bias = the three size-2 tensors in appearance order.
// ---------------------------------------------------------------------------
extern "C" void kernel_launch(void* const* d_in, const int* in_sizes, int n_in,
                              void* d_out, int out_size)
{
    int i_x = -1, i_eidx = -1, i_attr = -1, i_W = -1;
    int small[3] = {-1, -1, -1};
    int nsmall = 0;
    {
        long long best = -1;
        for (int i = 0; i < n_in; i++)
            if (in_sizes[i] > best) { best = in_sizes[i]; i_x = i; }
        best = -1;
        for (int i = 0; i < n_in; i++)
            if (i != i_x && in_sizes[i] > best) { best = in_sizes[i]; i_eidx = i; }
        best = -1;
        for (int i = 0; i < n_in; i++)
            if (i != i_x && i != i_eidx && in_sizes[i] > best) { best = in_sizes[i]; i_attr = i; }
    }
    for (int i = 0; i < n_in; i++) {
        if (i == i_x || i == i_eidx || i == i_attr) continue;
        if (in_sizes[i] > 16) { i_W = i; }
        else if (nsmall < 3) { small[nsmall++] = i; }
    }

    const float* x       = (const float*)d_in[i_x];
    const void*  eidx    = d_in[i_eidx];
    const float* W       = (const float*)d_in[i_W];
    const float* att_src = (const float*)d_in[small[0]];
    const float* att_dst = (const float*)d_in[small[1]];
    const float* bias    = (const float*)d_in[small[2]];
    float* out           = (float*)d_out;

    int N = in_sizes[i_x] / IN_DIM;
    int E = in_sizes[i_attr];               // edge_attr is [E,1]
    int eidx_elems = in_sizes[i_eidx];

    // dtype: ratio 4 => int64 reported as word count (det_nwords=0 => force 64).
    // ratio 2 => ambiguous; K1 block 0 samples odd words on device.
    int det_nwords = (eidx_elems == 4 * E) ? 0 : (2 * E);

    // W -> constant bank (D2D async copy; graph-capturable)
    cudaMemcpyToSymbolAsync(cW, W, 2 * IN_DIM * sizeof(float), 0,
                            cudaMemcpyDeviceToDevice);

    // K1: thread-per-node, smem-transposed tiles; 391 blocks (one wave)
    int blocks1 = (N + 255) / 256;
    gat_project_kernel<<<blocks1, 256>>>(x, att_src, att_dst,
                                         (const int*)eidx, det_nwords, N);

    // K2: ILP=4 edges per thread, full grid
    int blocks2 = (E + 256 * EDGE_ILP - 1) / (256 * EDGE_ILP);
    gat_edge_kernel<<<blocks2, 256>>>(eidx, E, N);

    // K3: normalize + bias, 2 nodes/thread
    int pairs = (N + 1) / 2;
    gat_final_kernel<<<(pairs + 255) / 256, 256>>>(out, bias, N);
}

// round 9
// speedup vs baseline: 1.1153x; 1.1040x over previous
#include <cuda_runtime.h>
#include <cstdint>

#define MAX_N 100000
#define IN_DIM 192
#define NEG_SLOPE 0.2f
#define EDGE_ILP 4

// Scratch (allocation-free rule: __device__ globals).
// g_rec[n]  = {xproj0, xproj1, a_src, a_dst}
// g_adst[n] = a_dst packed (dense -> better L1 behavior on gathers)
// g_acc[n]  = {sum e*xp0, sum e*xp1, sum e, pad}
__device__ float4 g_rec[MAX_N];
__device__ float  g_adst[MAX_N];
__device__ float4 g_acc[MAX_N];
__device__ int    g_is64;   // 1 if edge_index is int64, 0 if int32

// ---------------------------------------------------------------------------
// Kernel 1: projection + logits + self-loop init. Warp-per-node structure
// (R6, 22.2us) upgraded to TWO nodes per warp-iteration: two independent
// load->FFMA chains and four independent shuffle-reduce chains in flight,
// doubling latency hiding at the same instruction count per node.
// Block 0 warp 0 additionally runs the int64/int32 detector.
// ---------------------------------------------------------------------------
__global__ __launch_bounds__(256)
void gat_project_kernel(const float* __restrict__ x,
                        const float* __restrict__ W,        // [IN_DIM,2]
                        const float* __restrict__ att_src,  // [2]
                        const float* __restrict__ att_dst,  // [2]
                        const int* __restrict__ eidx_w,     // edge_index words
                        int det_nwords,                     // 0 => force is64=1
                        int N)
{
    if (blockIdx.x == 0 && threadIdx.x < 32) {
        int notz = 0;
        if (det_nwords > 0) {
            for (int i = threadIdx.x; i < 2048; i += 32) {
                int p = 2 * i + 1;                 // odd 32-bit words
                if (p < det_nwords && eidx_w[p] != 0) notz = 1;
            }
        }
        notz = __any_sync(0xffffffffu, notz);
        if (threadIdx.x == 0) g_is64 = (det_nwords > 0) ? (notz ? 0 : 1) : 1;
    }

    int lane  = threadIdx.x & 31;
    int warp  = (blockIdx.x * blockDim.x + threadIdx.x) >> 5;
    int nwarp = (gridDim.x * blockDim.x) >> 5;

    // W float4 q covers rows 2q,2q+1 -> {W[2q][0],W[2q][1],W[2q+1][0],W[2q+1][1]}
    const float4* W4 = (const float4*)W;
    float4 w0 = __ldg(W4 + lane);
    float4 w1 = __ldg(W4 + lane + 32);
    float4 w2 = __ldg(W4 + lane + 64);
    float as0 = __ldg(att_src + 0), as1 = __ldg(att_src + 1);
    float ad0 = __ldg(att_dst + 0), ad1 = __ldg(att_dst + 1);

    for (int n0 = 2 * warp; n0 < N; n0 += 2 * nwarp) {
        int nA = n0;
        int nB = (n0 + 1 < N) ? (n0 + 1) : n0;     // clamp (safe duplicate load)

        const float2* xrA = (const float2*)(x + (size_t)nA * IN_DIM);
        const float2* xrB = (const float2*)(x + (size_t)nB * IN_DIM);
        float2 a0 = __ldg(xrA + lane);
        float2 b0 = __ldg(xrB + lane);
        float2 a1 = __ldg(xrA + lane + 32);
        float2 b1 = __ldg(xrB + lane + 32);
        float2 a2 = __ldg(xrA + lane + 64);
        float2 b2 = __ldg(xrB + lane + 64);

        float pA0 = a0.x * w0.x + a0.y * w0.z
                  + a1.x * w1.x + a1.y * w1.z
                  + a2.x * w2.x + a2.y * w2.z;
        float pA1 = a0.x * w0.y + a0.y * w0.w
                  + a1.x * w1.y + a1.y * w1.w
                  + a2.x * w2.y + a2.y * w2.w;
        float pB0 = b0.x * w0.x + b0.y * w0.z
                  + b1.x * w1.x + b1.y * w1.z
                  + b2.x * w2.x + b2.y * w2.z;
        float pB1 = b0.x * w0.y + b0.y * w0.w
                  + b1.x * w1.y + b1.y * w1.w
                  + b2.x * w2.y + b2.y * w2.w;

#pragma unroll
        for (int off = 16; off > 0; off >>= 1) {   // 4 independent chains
            pA0 += __shfl_xor_sync(0xffffffffu, pA0, off);
            pA1 += __shfl_xor_sync(0xffffffffu, pA1, off);
            pB0 += __shfl_xor_sync(0xffffffffu, pB0, off);
            pB1 += __shfl_xor_sync(0xffffffffu, pB1, off);
        }

        if (lane == 0) {
            {
                float a_s = pA0 * as0 + pA1 * as1;
                float a_d = pA0 * ad0 + pA1 * ad1;
                g_rec[nA]  = make_float4(pA0, pA1, a_s, a_d);
                g_adst[nA] = a_d;
                float alpha = a_s + a_d;           // self-loop edge
                alpha = (alpha >= 0.f) ? alpha : NEG_SLOPE * alpha;
                float ev = __expf(alpha);
                g_acc[nA] = make_float4(ev * pA0, ev * pA1, ev, 0.f);
            }
            if (n0 + 1 < N) {
                float a_s = pB0 * as0 + pB1 * as1;
                float a_d = pB0 * ad0 + pB1 * ad1;
                g_rec[nB]  = make_float4(pB0, pB1, a_s, a_d);
                g_adst[nB] = a_d;
                float alpha = a_s + a_d;
                alpha = (alpha >= 0.f) ? alpha : NEG_SLOPE * alpha;
                float ev = __expf(alpha);
                g_acc[nB] = make_float4(ev * pB0, ev * pB1, ev, 0.f);
            }
        }
    }
}

// ---------------------------------------------------------------------------
// Kernel 2 (unchanged from R6): single fused pass over edges, ILP=4.
//   alpha = leakyrelu(a_src[s] + a_dst[d]); e = exp(alpha)
//   acc[d] += {e*xp0[s], e*xp1[s], e, 0}  via one red.global.add.v4.f32
// (softmax max-subtraction elided: scale-invariant; fp32-safe here)
// ---------------------------------------------------------------------------
__global__ __launch_bounds__(256)
void gat_edge_kernel(const void* __restrict__ edge_index, int E, int N)
{
    int base = blockIdx.x * (256 * EDGE_ILP) + threadIdx.x;
    int is64 = g_is64;
    bool full = (blockIdx.x + 1) * (256 * EDGE_ILP) <= E;

    int s[EDGE_ILP], d[EDGE_ILP];
    if (full) {
#pragma unroll
        for (int i = 0; i < EDGE_ILP; i++) {
            int e = base + i * 256;
            if (is64) {
                const long long* ei = (const long long*)edge_index;
                s[i] = (int)__ldg(ei + e);
                d[i] = (int)__ldg(ei + E + e);
            } else {
                const int* ei = (const int*)edge_index;
                s[i] = __ldg(ei + e);
                d[i] = __ldg(ei + E + e);
            }
        }
    } else {
#pragma unroll
        for (int i = 0; i < EDGE_ILP; i++) {
            int e = base + i * 256;
            s[i] = -1; d[i] = -1;
            if (e < E) {
                if (is64) {
                    const long long* ei = (const long long*)edge_index;
                    s[i] = (int)__ldg(ei + e);
                    d[i] = (int)__ldg(ei + E + e);
                } else {
                    const int* ei = (const int*)edge_index;
                    s[i] = __ldg(ei + e);
                    d[i] = __ldg(ei + E + e);
                }
            }
        }
    }

    float4 rs[EDGE_ILP];
    float  ad[EDGE_ILP];
#pragma unroll
    for (int i = 0; i < EDGE_ILP; i++) {
        if ((unsigned)s[i] < (unsigned)N && (unsigned)d[i] < (unsigned)N) {
            rs[i] = __ldg(&g_rec[s[i]]);        // 16B gather
            ad[i] = __ldg(&g_adst[d[i]]);       // 4B gather, dense array
        }
    }

#pragma unroll
    for (int i = 0; i < EDGE_ILP; i++) {
        if ((unsigned)s[i] < (unsigned)N && (unsigned)d[i] < (unsigned)N) {
            float alpha = rs[i].z + ad[i];
            alpha = (alpha >= 0.f) ? alpha : NEG_SLOPE * alpha;
            float ev = __expf(alpha);
            float v0 = ev * rs[i].x;
            float v1 = ev * rs[i].y;
            asm volatile("red.global.add.v4.f32 [%0], {%1, %2, %3, %4};"
                         :: "l"(&g_acc[d[i]]), "f"(v0), "f"(v1), "f"(ev), "f"(0.f)
                         : "memory");
        }
    }
}

// ---------------------------------------------------------------------------
// Kernel 3: normalize + bias. 2 nodes/thread, packed float4 store.
// ---------------------------------------------------------------------------
__global__ __launch_bounds__(256)
void gat_final_kernel(float* __restrict__ out,
                      const float* __restrict__ bias,
                      int N)
{
    int i = blockIdx.x * blockDim.x + threadIdx.x;   // pair index
    int n0 = 2 * i;
    if (n0 >= N) return;
    float b0 = __ldg(bias + 0), b1 = __ldg(bias + 1);

    float4 a0 = g_acc[n0];
    float inv0 = 1.0f / (a0.z + 1e-16f);
    if (n0 + 1 < N) {
        float4 a1 = g_acc[n0 + 1];
        float inv1 = 1.0f / (a1.z + 1e-16f);
        float4 o = make_float4(a0.x * inv0 + b0, a0.y * inv0 + b1,
                               a1.x * inv1 + b0, a1.y * inv1 + b1);
        ((float4*)out)[i] = o;
    } else {
        ((float2*)out)[n0] = make_float2(a0.x * inv0 + b0, a0.y * inv0 + b1);
    }
}

// ---------------------------------------------------------------------------
// Input identification by element count (robust to metadata ordering):
//   x = largest; edge_index = 2nd; edge_attr = 3rd (gives E); W = 384;
//   att_src, att_dst, bias = the three size-2 tensors in appearance order.
// ---------------------------------------------------------------------------
extern "C" void kernel_launch(void* const* d_in, const int* in_sizes, int n_in,
                              void* d_out, int out_size)
{
    int i_x = -1, i_eidx = -1, i_attr = -1, i_W = -1;
    int small[3] = {-1, -1, -1};
    int nsmall = 0;
    {
        long long best = -1;
        for (int i = 0; i < n_in; i++)
            if (in_sizes[i] > best) { best = in_sizes[i]; i_x = i; }
        best = -1;
        for (int i = 0; i < n_in; i++)
            if (i != i_x && in_sizes[i] > best) { best = in_sizes[i]; i_eidx = i; }
        best = -1;
        for (int i = 0; i < n_in; i++)
            if (i != i_x && i != i_eidx && in_sizes[i] > best) { best = in_sizes[i]; i_attr = i; }
    }
    for (int i = 0; i < n_in; i++) {
        if (i == i_x || i == i_eidx || i == i_attr) continue;
        if (in_sizes[i] > 16) { i_W = i; }
        else if (nsmall < 3) { small[nsmall++] = i; }
    }

    const float* x       = (const float*)d_in[i_x];
    const void*  eidx    = d_in[i_eidx];
    const float* W       = (const float*)d_in[i_W];
    const float* att_src = (const float*)d_in[small[0]];
    const float* att_dst = (const float*)d_in[small[1]];
    const float* bias    = (const float*)d_in[small[2]];
    float* out           = (float*)d_out;

    int N = in_sizes[i_x] / IN_DIM;
    int E = in_sizes[i_attr];               // edge_attr is [E,1]
    int eidx_elems = in_sizes[i_eidx];

    // dtype: ratio 4 => int64 reported as word count (det_nwords=0 => force 64).
    // ratio 2 => ambiguous; K1 block 0 samples odd words on device.
    int det_nwords = (eidx_elems == 4 * E) ? 0 : (2 * E);

    // K1: persistent warp loop, 2 nodes per warp-iteration
    gat_project_kernel<<<1184, 256>>>(x, W, att_src, att_dst,
                                      (const int*)eidx, det_nwords, N);

    // K2: ILP=4 edges per thread, full grid
    int blocks2 = (E + 256 * EDGE_ILP - 1) / (256 * EDGE_ILP);
    gat_edge_kernel<<<blocks2, 256>>>(eidx, E, N);

    // K3: normalize + bias, 2 nodes/thread
    int pairs = (N + 1) / 2;
    gat_final_kernel<<<(pairs + 255) / 256, 256>>>(out, bias, N);
}